// round 15
// baseline (speedup 1.0000x reference)
#include <cuda_runtime.h>
#include <cuda_fp16.h>
#include <math.h>
#include <cstdint>

// ---------------- problem constants ----------------
#define VV     32000
#define MM     512
#define NLEAF  16384
#define DD     8
#define NNODE  4096
#define KCH    4
#define BB     64
#define SSEQ   16
#define POOLSZ (1 + NLEAF + DD * NNODE)   // 49153
#define OFFS   (1 + NLEAF)                // 16385
#define G3M    (3 * MM)                   // 1536
#define NALL   (DD * NNODE)               // 32768

__device__ __forceinline__ float sigf(float x) { return 1.0f / (1.0f + expf(-x)); }

__device__ __forceinline__ uint32_t smem_u32(const void* p) {
    uint32_t a;
    asm("{ .reg .u64 t; cvta.to.shared.u64 t, %1; cvt.u32.u64 %0, t; }" : "=r"(a) : "l"(p));
    return a;
}

__device__ __forceinline__ uint32_t f2h(float x, float y) {
    __half2 h = __floats2half2_rn(x, y);
    return *reinterpret_cast<uint32_t*>(&h);
}
__device__ __forceinline__ float2 h2f(uint32_t w) {
    __half2 h = *reinterpret_cast<__half2*>(&w);
    return __half22float2(h);
}
__device__ __forceinline__ void packres(float x, float y, uint32_t& hi, uint32_t& lo) {
    hi = f2h(x, y);
    float2 f = h2f(hi);
    lo = f2h(x - f.x, y - f.y);
}

#define MMA_F16(c, a0, a1, a2, a3, b0, b1) \
    asm volatile("mma.sync.aligned.m16n8k16.row.col.f32.f16.f16.f32 " \
        "{%0,%1,%2,%3}, {%4,%5,%6,%7}, {%8,%9}, {%0,%1,%2,%3};" \
        : "+f"((c)[0]), "+f"((c)[1]), "+f"((c)[2]), "+f"((c)[3]) \
        : "r"(a0), "r"(a1), "r"(a2), "r"(a3), "r"(b0), "r"(b1))

#define LDSM_X4(r0, r1, r2, r3, addr) \
    asm volatile("ldmatrix.sync.aligned.m8n8.x4.shared.b16 {%0,%1,%2,%3}, [%4];" \
        : "=r"(r0), "=r"(r1), "=r"(r2), "=r"(r3) : "r"(addr))

#define CP_ASYNC16(dst, src) \
    asm volatile("cp.async.cg.shared.global [%0], [%1], 16;" :: "r"(dst), "l"(src))
#define CP_COMMIT() asm volatile("cp.async.commit_group;")
#define CP_WAIT1()  asm volatile("cp.async.wait_group 1;")
#define CP_WAIT0()  asm volatile("cp.async.wait_group 0;")

// ---------------- device scratch ----------------
__device__ float g_c_pool[(size_t)POOLSZ * MM];
__device__ float g_biasbig[2048];
__device__ float g_bihcat[2 * G3M];
__device__ unsigned g_bar;
// fp16 planes
__device__ __half g_HW[(size_t)POOLSZ * MM];        // fp16 C
__device__ __half g_IOUFall[(size_t)NALL * 2048];   // fp16 C
__device__ __half g_W1[(size_t)2048 * MM];
__device__ __half g_W2[(size_t)G3M * MM];
__device__ __half g_WfT[(size_t)MM * MM];
__device__ __half g_wih[2][(size_t)G3M * MM];
__device__ __half g_Xall[(size_t)NALL * MM];
__device__ __half g_SUMH[(size_t)NNODE * MM];
__device__ __half g_Hhi[(size_t)POOLSZ * MM];
__device__ __half g_Hlo[(size_t)POOLSZ * MM];
__device__ __half g_xs[(size_t)BB * SSEQ * MM];
// GRU (fp32)
__device__ float g_xg[(size_t)BB * SSEQ * 2 * G3M];
__device__ float g_hg[2][(size_t)BB * G3M];
__device__ float g_hst[2][(size_t)BB * MM];

// ---------------- fp16 1-pass mma GEMM ----------------
// outmode: 0 = fp32 C + bias, 2 = fp16 C + bias, 3 = fp16 C accumulate
#define RS 20
#define PLANE 2560
#define STG_BYTES 20480
#define MMA_SMEM_BYTES (2 * STG_BYTES)

__device__ __forceinline__ void gemm_body(
    const uint32_t* pA, const uint32_t* pB,
    int mbase, int nbase, int K, const float* bias, void* C, int ldC, int outmode,
    uint32_t smb) {
    const int tid = threadIdx.x;
    const int w = tid >> 5, lane = tid & 31;
    const int warpM = w & 1, warpN = w >> 1;
    const int Kw = K >> 1;
    const int nCh = Kw >> 4;

    float acc[4][4][4];
#pragma unroll
    for (int i = 0; i < 4; i++)
#pragma unroll
        for (int j = 0; j < 4; j++)
#pragma unroll
            for (int q = 0; q < 4; q++) acc[i][j][q] = 0.f;

    const int lrow = lane & 15, lcol = lane >> 4;
    uint32_t aAddr[4], bAddr[2];
#pragma unroll
    for (int i = 0; i < 4; i++)
        aAddr[i] = smb + (uint32_t)(((warpM * 64 + i * 16 + lrow) * RS + lcol * 4) * 4);
#pragma unroll
    for (int jp = 0; jp < 2; jp++)
        bAddr[jp] = smb + (uint32_t)(PLANE * 4 + ((warpN * 32 + jp * 16 + lrow) * RS + lcol * 4) * 4);

#define ISSUE(tw) do {                                                            \
    const int kw0 = (tw) * 16;                                                    \
    const uint32_t sb = smb + (uint32_t)(((tw) & 1) * STG_BYTES);                 \
    _Pragma("unroll")                                                             \
    for (int q = 0; q < 4; q++) {                                                 \
        const int pl = q >> 1;                                                    \
        int s = tid + (q & 1) * 256;                                              \
        int r = s >> 2, sg = s & 3;                                               \
        const uint32_t* src = (pl == 0 ? pA : pB)                                 \
            + (size_t)((pl == 0 ? mbase : nbase) + r) * Kw + kw0 + sg * 4;        \
        uint32_t dst = sb + (uint32_t)((pl * PLANE + r * RS + sg * 4) * 4);       \
        CP_ASYNC16(dst, src);                                                     \
    }                                                                             \
    CP_COMMIT(); } while (0)

    ISSUE(0);
    if (nCh > 1) ISSUE(1);

    for (int t = 0; t < nCh; t++) {
        if (t + 1 < nCh) CP_WAIT1(); else CP_WAIT0();
        __syncthreads();

        const uint32_t so = (uint32_t)((t & 1) * STG_BYTES);
#pragma unroll
        for (int ks = 0; ks < 2; ks++) {
            const uint32_t ko = so + ks * 32;
            uint32_t Bf[4][2];
#pragma unroll
            for (int jp = 0; jp < 2; jp++) {
                LDSM_X4(Bf[2 * jp][0], Bf[2 * jp + 1][0], Bf[2 * jp][1], Bf[2 * jp + 1][1],
                        bAddr[jp] + ko);
            }
#pragma unroll
            for (int i = 0; i < 4; i++) {
                uint32_t A0, A1, A2, A3;
                LDSM_X4(A0, A1, A2, A3, aAddr[i] + ko);
#pragma unroll
                for (int j = 0; j < 4; j++)
                    MMA_F16(acc[i][j], A0, A1, A2, A3, Bf[j][0], Bf[j][1]);
            }
        }
        if (t + 2 < nCh) {
            __syncthreads();
            ISSUE(t + 2);
        }
    }
#undef ISSUE

    const int g = lane >> 2, tg = lane & 3;
#pragma unroll
    for (int i = 0; i < 4; i++) {
#pragma unroll
        for (int j = 0; j < 4; j++) {
            int row = mbase + warpM * 64 + i * 16 + g;
            int col = nbase + warpN * 32 + j * 8 + tg * 2;
            float a0 = acc[i][j][0], a1 = acc[i][j][1];
            float a2 = acc[i][j][2], a3 = acc[i][j][3];
            if (outmode == 0) {
                float* c0p = (float*)C + (size_t)row * ldC + col;
                float* c1p = (float*)C + (size_t)(row + 8) * ldC + col;
                float b0v = bias[col], b1v = bias[col + 1];
                *(float2*)c0p = make_float2(a0 + b0v, a1 + b1v);
                *(float2*)c1p = make_float2(a2 + b0v, a3 + b1v);
            } else {
                __half2* c0p = (__half2*)((__half*)C + (size_t)row * ldC + col);
                __half2* c1p = (__half2*)((__half*)C + (size_t)(row + 8) * ldC + col);
                if (outmode == 3) {
                    float2 e0 = __half22float2(*c0p);
                    float2 e1 = __half22float2(*c1p);
                    a0 += e0.x; a1 += e0.y; a2 += e1.x; a3 += e1.y;
                } else {
                    float b0v = bias[col], b1v = bias[col + 1];
                    a0 += b0v; a1 += b1v; a2 += b0v; a3 += b1v;
                }
                *c0p = __floats2half2_rn(a0, a1);
                *c1p = __floats2half2_rn(a2, a3);
            }
        }
    }
}

__global__ void __launch_bounds__(256)
mma_gemm(const __half* __restrict__ A, const __half* __restrict__ B,
         const float* __restrict__ bias, void* __restrict__ C, int ldC, int K, int outmode) {
    extern __shared__ uint32_t sm[];
    gemm_body((const uint32_t*)A, (const uint32_t*)B,
              blockIdx.y * 128, blockIdx.x * 128, K, bias, C, ldC, outmode, smem_u32(sm));
}

// dual: bx<12 -> IOU accum fp16; bx>=12 -> HW fp16
__global__ void __launch_bounds__(256)
mma_gemm_dual(const __half* __restrict__ A1, const __half* __restrict__ A2,
              const __half* __restrict__ B1, const __half* __restrict__ B2,
              const float* __restrict__ bias2, __half* __restrict__ C1, __half* __restrict__ C2) {
    extern __shared__ uint32_t sm[];
    if (blockIdx.x < 12) {
        gemm_body((const uint32_t*)A1, (const uint32_t*)B1,
                  blockIdx.y * 128, blockIdx.x * 128, 512, nullptr, C1, 2048, 3, smem_u32(sm));
    } else {
        gemm_body((const uint32_t*)A2, (const uint32_t*)B2,
                  blockIdx.y * 128, (blockIdx.x - 12) * 128, 512, bias2, C2, 512, 2, smem_u32(sm));
    }
}

// ---------------- prep: tiled transpose -> fp16 ----------------
__global__ void __launch_bounds__(256)
transp_h(const float* __restrict__ srcA, const float* __restrict__ srcB,
         int ldA, int ldB, int nsplit, int K, __half* __restrict__ dst) {
    __shared__ float tile[32][33];
    const int n0 = blockIdx.x * 32, k0 = blockIdx.y * 32;
    const int tx = threadIdx.x, ty = threadIdx.y;
    const int n = n0 + tx;
    const float* src = (n0 < nsplit) ? srcA : srcB;
    const int ld = (n0 < nsplit) ? ldA : ldB;
    const int col = (n0 < nsplit) ? n : n - nsplit;
#pragma unroll
    for (int i = 0; i < 4; i++) {
        int k = k0 + ty + i * 8;
        tile[ty + i * 8][tx] = src[(size_t)k * ld + col];
    }
    __syncthreads();
    const int Kw = K >> 1;
#pragma unroll
    for (int j = 0; j < 2; j++) {
        int lin = j * 256 + ty * 32 + tx;
        int nl = lin >> 4, kp = lin & 15;
        uint32_t h = f2h(tile[kp * 2][nl], tile[kp * 2 + 1][nl]);
        ((uint32_t*)dst)[(size_t)(n0 + nl) * Kw + (k0 >> 1) + kp] = h;
    }
}

// wih fp16 + biases + zero-inits (merged)
__global__ void prep_init(const float* __restrict__ wih_f, const float* __restrict__ wih_b,
                          const float* __restrict__ bioux, const float* __restrict__ biouh,
                          const float* __restrict__ bfx,
                          const float* __restrict__ bih_f, const float* __restrict__ bih_b) {
    int idx = blockIdx.x * blockDim.x + threadIdx.x;
    const int T2 = G3M * (MM / 2);
    if (idx < 2 * T2) {
        int dir = idx / T2, j = idx % T2;
        const float* wsrc = dir ? wih_b : wih_f;
        ((uint32_t*)g_wih[dir])[j] = f2h(wsrc[2 * j], wsrc[2 * j + 1]);
    }
    if (idx < 2048)
        g_biasbig[idx] = (idx < G3M) ? (bioux[idx] + biouh[idx]) : bfx[idx - G3M];
    if (idx < 2 * G3M)
        g_bihcat[idx] = (idx < G3M) ? bih_f[idx] : bih_b[idx - G3M];
    if (idx == 0) g_bar = 0u;
    if (idx < MM / 2) {
        ((uint32_t*)g_Hhi)[idx] = 0u;
        ((uint32_t*)g_Hlo)[idx] = 0u;
    }
    if (idx < 2 * BB * MM) (&g_hst[0][0])[idx] = 0.f;
}

// ---------------- init leaves ----------------
__global__ void init_leaf(const float* __restrict__ embed, const int* __restrict__ leaf_idx) {
    int idx = blockIdx.x * blockDim.x + threadIdx.x;
    if (idx >= NLEAF * (MM / 4)) return;
    int n = idx >> 7, m = (idx & 127) * 4;
    int w = leaf_idx[n];
    float4 v = *(const float4*)(embed + (size_t)w * MM + m);
    uint32_t h0, l0, h1, l1;
    packres(v.x, v.y, h0, l0);
    packres(v.z, v.w, h1, l1);
    size_t wrd = ((size_t)(1 + n) * MM + m) >> 1;
    ((uint32_t*)g_Hhi)[wrd] = h0; ((uint32_t*)g_Hhi)[wrd + 1] = h1;
    ((uint32_t*)g_Hlo)[wrd] = l0; ((uint32_t*)g_Hlo)[wrd + 1] = l1;
}

// ---------------- gather x embeddings for ALL levels ----------------
__global__ void gather_x_all(const float* __restrict__ embed, const int* __restrict__ lwi) {
    int idx = blockIdx.x * blockDim.x + threadIdx.x;
    if (idx >= NALL * (MM / 4)) return;
    int ng = idx >> 7, m = (idx & 127) * 4;
    int w = lwi[ng];
    float4 x = *(const float4*)(embed + (size_t)w * MM + m);
    size_t wrd = ((size_t)ng * MM + m) >> 1;
    ((uint32_t*)g_Xall)[wrd]     = f2h(x.x, x.y);
    ((uint32_t*)g_Xall)[wrd + 1] = f2h(x.z, x.w);
}

// ---------------- per-level gather: sum of child h (reconstruct hi+lo) ----------------
__global__ void gather_level(const int* __restrict__ child, int d) {
    int idx = blockIdx.x * blockDim.x + threadIdx.x;
    if (idx >= NNODE * (MM / 4)) return;
    int n = idx >> 7, m = (idx & 127) * 4;
    float4 s = make_float4(0.f, 0.f, 0.f, 0.f);
    const int* ch = child + ((size_t)d * NNODE + n) * KCH;
#pragma unroll
    for (int k = 0; k < KCH; k++) {
        int ci = ch[k];
        size_t wrd = ((size_t)ci * MM + m) >> 1;
        uint2 hw = *(const uint2*)((const uint32_t*)g_Hhi + wrd);
        uint2 lw = *(const uint2*)((const uint32_t*)g_Hlo + wrd);
        float2 a0 = h2f(hw.x), b0 = h2f(lw.x);
        float2 a1 = h2f(hw.y), b1 = h2f(lw.y);
        s.x += a0.x + b0.x; s.y += a0.y + b0.y;
        s.z += a1.x + b1.x; s.w += a1.y + b1.y;
    }
    size_t wrd = ((size_t)n * MM + m) >> 1;
    ((uint32_t*)g_SUMH)[wrd]     = f2h(s.x, s.y);
    ((uint32_t*)g_SUMH)[wrd + 1] = f2h(s.z, s.w);
}

// ---------------- level pointwise (fp16 IOUF/HW reads) ----------------
__global__ void level_point(const int* __restrict__ child, int d) {
    int idx = blockIdx.x * blockDim.x + threadIdx.x;
    if (idx >= NNODE * (MM / 2)) return;
    int n = idx >> 8, j = idx & 255;
    int m = 2 * j;
    const __half* row = g_IOUFall + (size_t)(d * NNODE + n) * 2048;
    float2 iv = __half22float2(*(const __half2*)(row + m));
    float2 ov = __half22float2(*(const __half2*)(row + MM + m));
    float2 uv = __half22float2(*(const __half2*)(row + 2 * MM + m));
    float2 fx = __half22float2(*(const __half2*)(row + 3 * MM + m));
    float c0 = sigf(iv.x) * tanhf(uv.x);
    float c1 = sigf(iv.y) * tanhf(uv.y);
    const int* ch = child + ((size_t)d * NNODE + n) * KCH;
#pragma unroll
    for (int k = 0; k < KCH; k++) {
        int ci = ch[k];
        if (ci > NLEAF) {
            float2 hw = __half22float2(*(const __half2*)(g_HW + (size_t)ci * MM + m));
            float2 cc = *(const float2*)(g_c_pool + (size_t)ci * MM + m);
            c0 += sigf(fx.x + hw.x) * cc.x;
            c1 += sigf(fx.y + hw.y) * cc.y;
        }
    }
    float h0 = sigf(ov.x) * tanhf(c0);
    float h1 = sigf(ov.y) * tanhf(c1);
    size_t slot = (size_t)(OFFS + d * NNODE + n) * MM + m;
    *(float2*)(g_c_pool + slot) = make_float2(c0, c1);
    uint32_t sh, sl; packres(h0, h1, sh, sl);
    ((uint32_t*)g_Hhi)[slot >> 1] = sh;
    ((uint32_t*)g_Hlo)[slot >> 1] = sl;
}

// ---------------- GRU ----------------
__global__ void gather_xs(const int* __restrict__ ctx) {
    int idx = blockIdx.x * blockDim.x + threadIdx.x;
    if (idx >= BB * SSEQ * (MM / 4)) return;
    int rowI = idx >> 7, m = (idx & 127) * 4;
    int p = ctx[rowI];
    size_t swrd = ((size_t)p * MM + m) >> 1;
    uint2 hw = *(const uint2*)((const uint32_t*)g_Hhi + swrd);
    uint2 lw = *(const uint2*)((const uint32_t*)g_Hlo + swrd);
    float2 a0 = h2f(hw.x), b0 = h2f(lw.x);
    float2 a1 = h2f(hw.y), b1 = h2f(lw.y);
    size_t wrd = ((size_t)rowI * MM + m) >> 1;
    ((uint32_t*)g_xs)[wrd]     = f2h(a0.x + b0.x, a0.y + b0.y);
    ((uint32_t*)g_xs)[wrd + 1] = f2h(a1.x + b1.x, a1.y + b1.y);
}

#define GNB 96
#define HS_STR 516
__device__ __forceinline__ void gridbar(unsigned gen) {
    __syncthreads();
    if (threadIdx.x == 0) {
        __threadfence();
        atomicAdd(&g_bar, 1u);
        while (atomicAdd(&g_bar, 0u) < gen * GNB) { __nanosleep(64); }
        __threadfence();
    }
    __syncthreads();
}

__global__ void __launch_bounds__(256) gru_persist(const float* __restrict__ whh_f,
                                                   const float* __restrict__ whh_b,
                                                   const float* __restrict__ bhh_f,
                                                   const float* __restrict__ bhh_b,
                                                   float* __restrict__ out) {
    extern __shared__ float sh[];
    float* Hs = sh;                     // 64 x HS_STR
    float* Ws = sh + 64 * HS_STR;       // k-major [512][32]
    const int dir = blockIdx.y;
    const int n0 = blockIdx.x * 32;
    const int tid = threadIdx.x;
    const int bid = blockIdx.y * 48 + blockIdx.x;
    const float* whh = dir ? whh_b : whh_f;
    const float* bhh = dir ? bhh_b : bhh_f;

    for (int i = tid; i < 32 * 512; i += 256) {
        int k = i & 511, col = i >> 9;
        Ws[k * 32 + col] = whh[(size_t)(n0 + col) * MM + k];
    }
    const int cg = tid & 7, r = tid >> 3;
    float bv[4];
#pragma unroll
    for (int c = 0; c < 4; c++) bv[c] = bhh[n0 + cg * 4 + c];

    unsigned gen = 0;
    for (int t = 0; t < SSEQ; t++) {
        __syncthreads();
        const float* H = g_hst[dir];
        for (int i = tid; i < 64 * 512; i += 256) Hs[(i >> 9) * HS_STR + (i & 511)] = H[i];
        __syncthreads();
        int row0 = 2 * r, row1 = row0 + 1;
        float acc0[4] = {0.f, 0.f, 0.f, 0.f};
        float acc1[4] = {0.f, 0.f, 0.f, 0.f};
        for (int k = 0; k < 512; k += 4) {
            float4 ha = *(float4*)&Hs[row0 * HS_STR + k];
            float4 hb = *(float4*)&Hs[row1 * HS_STR + k];
#pragma unroll
            for (int i = 0; i < 4; i++) {
                float4 wv = *(float4*)&Ws[(k + i) * 32 + cg * 4];
                float a = (&ha.x)[i], b = (&hb.x)[i];
                acc0[0] += a * wv.x; acc0[1] += a * wv.y; acc0[2] += a * wv.z; acc0[3] += a * wv.w;
                acc1[0] += b * wv.x; acc1[1] += b * wv.y; acc1[2] += b * wv.z; acc1[3] += b * wv.w;
            }
        }
#pragma unroll
        for (int c = 0; c < 4; c++) {
            int n = n0 + cg * 4 + c;
            g_hg[dir][(size_t)row0 * G3M + n] = acc0[c] + bv[c];
            g_hg[dir][(size_t)row1 * G3M + n] = acc1[c] + bv[c];
        }
        gridbar(++gen);
        for (int e = bid * 256 + tid; e < 2 * BB * MM; e += GNB * 256) {
            int dd = e >> 15;
            int rem = e & 32767;
            int b = rem >> 9, j = rem & 511;
            int pos = dd ? (SSEQ - 1 - t) : t;
            const float* xrow = g_xg + (size_t)(b * SSEQ + pos) * (2 * G3M) + dd * G3M;
            const float* hrow = g_hg[dd] + (size_t)b * G3M;
            float rr_ = sigf(xrow[j] + hrow[j]);
            float zz = sigf(xrow[MM + j] + hrow[MM + j]);
            float nn = tanhf(xrow[2 * MM + j] + rr_ * hrow[2 * MM + j]);
            float hp = g_hst[dd][b * MM + j];
            float hn = (1.f - zz) * nn + zz * hp;
            g_hst[dd][b * MM + j] = hn;
            float* op = out + (size_t)(b * SSEQ + pos) * MM + j;
            if (t < 8) *op = hn; else *op += hn;
        }
        gridbar(++gen);
    }
}

// ---------------- host launch ----------------
extern "C" void kernel_launch(void* const* d_in, const int* in_sizes, int n_in,
                              void* d_out, int out_size) {
    const float* embed   = (const float*)d_in[0];
    const float* Wioux   = (const float*)d_in[1];
    const float* bioux   = (const float*)d_in[2];
    const float* Wiouh   = (const float*)d_in[3];
    const float* biouh   = (const float*)d_in[4];
    const float* Wfx     = (const float*)d_in[5];
    const float* bfx     = (const float*)d_in[6];
    const float* Wfh     = (const float*)d_in[7];
    const float* bfh     = (const float*)d_in[8];
    const float* wih_f   = (const float*)d_in[9];
    const float* whh_f   = (const float*)d_in[10];
    const float* bih_f   = (const float*)d_in[11];
    const float* bhh_f   = (const float*)d_in[12];
    const float* wih_b   = (const float*)d_in[13];
    const float* whh_b   = (const float*)d_in[14];
    const float* bih_b   = (const float*)d_in[15];
    const float* bhh_b   = (const float*)d_in[16];

    const int* leaf_idx = nullptr; const int* level_idx = nullptr;
    const int* child = nullptr; const int* ctx = nullptr;
    for (int i = 17; i < n_in; i++) {
        int sz = in_sizes[i];
        if (sz == NLEAF)                 leaf_idx  = (const int*)d_in[i];
        else if (sz == DD * NNODE)       level_idx = (const int*)d_in[i];
        else if (sz == DD * NNODE * KCH) child     = (const int*)d_in[i];
        else if (sz == BB * SSEQ)        ctx       = (const int*)d_in[i];
    }

    float* out = (float*)d_out;

    const size_t GRU_SMEM = (64 * HS_STR + 512 * 32) * sizeof(float);
    cudaFuncSetAttribute(mma_gemm, cudaFuncAttributeMaxDynamicSharedMemorySize, MMA_SMEM_BYTES);
    cudaFuncSetAttribute(mma_gemm_dual, cudaFuncAttributeMaxDynamicSharedMemorySize, MMA_SMEM_BYTES);
    cudaFuncSetAttribute(gru_persist, cudaFuncAttributeMaxDynamicSharedMemorySize, (int)GRU_SMEM);

    __half* d_Hhi;  cudaGetSymbolAddress((void**)&d_Hhi, g_Hhi);
    __half* d_X;    cudaGetSymbolAddress((void**)&d_X, g_Xall);
    __half* d_SH;   cudaGetSymbolAddress((void**)&d_SH, g_SUMH);
    __half* d_W1;   cudaGetSymbolAddress((void**)&d_W1, g_W1);
    __half* d_W2;   cudaGetSymbolAddress((void**)&d_W2, g_W2);
    __half* d_WfT;  cudaGetSymbolAddress((void**)&d_WfT, g_WfT);
    __half* d_wih;  cudaGetSymbolAddress((void**)&d_wih, g_wih);
    __half* d_xs;   cudaGetSymbolAddress((void**)&d_xs, g_xs);
    __half* d_IOUF; cudaGetSymbolAddress((void**)&d_IOUF, g_IOUFall);
    __half* d_HW;   cudaGetSymbolAddress((void**)&d_HW, g_HW);
    float* d_bb;    cudaGetSymbolAddress((void**)&d_bb, g_biasbig);
    float* d_bih;   cudaGetSymbolAddress((void**)&d_bih, g_bihcat);
    float* d_xg;    cudaGetSymbolAddress((void**)&d_xg, g_xg);

    // prep + init
    {
        dim3 blk(32, 8);
        transp_h<<<dim3(2048 / 32, 512 / 32), blk>>>(Wioux, Wfx, G3M, MM, G3M, 512, d_W1);
        transp_h<<<dim3(G3M / 32, 512 / 32), blk>>>(Wiouh, nullptr, G3M, 0, G3M, 512, d_W2);
        transp_h<<<dim3(MM / 32, 512 / 32), blk>>>(Wfh, nullptr, MM, 0, MM, 512, d_WfT);
    }
    prep_init<<<(2 * G3M * (MM / 2) + 255) / 256, 256>>>(wih_f, wih_b, bioux, biouh, bfx,
                                                         bih_f, bih_b);
    init_leaf<<<(NLEAF * (MM / 4) + 255) / 256, 256>>>(embed, leaf_idx);
    gather_x_all<<<(NALL * (MM / 4) + 255) / 256, 256>>>(embed, level_idx);

    // upfront: IOUF_all = X_all @ [Wioux|Wfx]^T + biasbig  (fp16 out)
    {
        dim3 grid(2048 / 128, NALL / 128);
        mma_gemm<<<grid, 256, MMA_SMEM_BYTES>>>(d_X, d_W1, d_bb, d_IOUF, 2048, 512, 2);
    }

    // level 0: IOU accum only (fp16 accum)
    gather_level<<<(NNODE * (MM / 4) + 255) / 256, 256>>>(child, 0);
    {
        dim3 grid(G3M / 128, NNODE / 128);
        mma_gemm<<<grid, 256, MMA_SMEM_BYTES>>>(d_SH, d_W2, nullptr, d_IOUF, 2048, 512, 3);
    }
    level_point<<<(NNODE * (MM / 2) + 255) / 256, 256>>>(child, 0);

    // levels 1..7: fused [IOU(d) accum | HW(d-1)]
    for (int d = 1; d < DD; d++) {
        gather_level<<<(NNODE * (MM / 4) + 255) / 256, 256>>>(child, d);
        size_t hoff = (size_t)(OFFS + (d - 1) * NNODE) * MM;
        {
            dim3 grid(16, NNODE / 128);
            mma_gemm_dual<<<grid, 256, MMA_SMEM_BYTES>>>(
                d_SH, d_Hhi + hoff, d_W2, d_WfT,
                bfh, d_IOUF + (size_t)d * NNODE * 2048, d_HW + hoff);
        }
        level_point<<<(NNODE * (MM / 2) + 255) / 256, 256>>>(child, d);
    }

    // GRU input gates: single GEMM, N=3072, fp32 out
    gather_xs<<<(BB * SSEQ * (MM / 4) + 255) / 256, 256>>>(ctx);
    {
        dim3 grid(2 * G3M / 128, (BB * SSEQ) / 128);
        mma_gemm<<<grid, 256, MMA_SMEM_BYTES>>>(d_xs, d_wih, d_bih, d_xg, 2 * G3M, 512, 0);
    }

    // GRU recurrence
    {
        dim3 grid(48, 2);
        gru_persist<<<grid, 256, GRU_SMEM>>>(whh_f, whh_b, bhh_f, bhh_b, out);
    }
}

// round 17
// speedup vs baseline: 1.3608x; 1.3608x over previous
#include <cuda_runtime.h>
#include <cuda_fp16.h>
#include <math.h>
#include <cstdint>

// ---------------- problem constants ----------------
#define VV     32000
#define MM     512
#define NLEAF  16384
#define DD     8
#define NNODE  4096
#define KCH    4
#define BB     64
#define SSEQ   16
#define POOLSZ (1 + NLEAF + DD * NNODE)   // 49153
#define OFFS   (1 + NLEAF)                // 16385
#define G3M    (3 * MM)                   // 1536
#define NALL   (DD * NNODE)               // 32768

__device__ __forceinline__ float sigf(float x) { return 1.0f / (1.0f + expf(-x)); }

__device__ __forceinline__ uint32_t smem_u32(const void* p) {
    uint32_t a;
    asm("{ .reg .u64 t; cvta.to.shared.u64 t, %1; cvt.u32.u64 %0, t; }" : "=r"(a) : "l"(p));
    return a;
}

__device__ __forceinline__ uint32_t f2h(float x, float y) {
    __half2 h = __floats2half2_rn(x, y);
    return *reinterpret_cast<uint32_t*>(&h);
}
__device__ __forceinline__ float2 h2f(uint32_t w) {
    __half2 h = *reinterpret_cast<__half2*>(&w);
    return __half22float2(h);
}

#define MMA_F16(c, a0, a1, a2, a3, b0, b1) \
    asm volatile("mma.sync.aligned.m16n8k16.row.col.f32.f16.f16.f32 " \
        "{%0,%1,%2,%3}, {%4,%5,%6,%7}, {%8,%9}, {%0,%1,%2,%3};" \
        : "+f"((c)[0]), "+f"((c)[1]), "+f"((c)[2]), "+f"((c)[3]) \
        : "r"(a0), "r"(a1), "r"(a2), "r"(a3), "r"(b0), "r"(b1))

#define LDSM_X4(r0, r1, r2, r3, addr) \
    asm volatile("ldmatrix.sync.aligned.m8n8.x4.shared.b16 {%0,%1,%2,%3}, [%4];" \
        : "=r"(r0), "=r"(r1), "=r"(r2), "=r"(r3) : "r"(addr))

#define CP_ASYNC16(dst, src) \
    asm volatile("cp.async.cg.shared.global [%0], [%1], 16;" :: "r"(dst), "l"(src))
#define CP_COMMIT() asm volatile("cp.async.commit_group;")
#define CP_WAIT1()  asm volatile("cp.async.wait_group 1;")
#define CP_WAIT0()  asm volatile("cp.async.wait_group 0;")

// ---------------- device scratch ----------------
__device__ float g_c_pool[(size_t)POOLSZ * MM];
__device__ float g_HW[(size_t)POOLSZ * MM];
__device__ float g_IOUFall[(size_t)NALL * 2048];
__device__ float g_biasbig[2048];
__device__ float g_bihcat[2 * G3M];
__device__ unsigned g_bar;
// fp16 planes (h pool stored hi-only: all consumers are fp16 GEMM operands)
__device__ __half g_W1[(size_t)2048 * MM];
__device__ __half g_W2[(size_t)G3M * MM];
__device__ __half g_WfT[(size_t)MM * MM];
__device__ __half g_wih[2][(size_t)G3M * MM];
__device__ __half g_Xall[(size_t)NALL * MM];
__device__ __half g_SUMH[(size_t)NNODE * MM];
__device__ __half g_Hhi[(size_t)POOLSZ * MM];
__device__ __half g_xs[(size_t)BB * SSEQ * MM];
// GRU (fp32)
__device__ float g_xg[(size_t)BB * SSEQ * 2 * G3M];
__device__ float g_hg[2][(size_t)BB * G3M];
__device__ float g_hst[2][(size_t)BB * MM];

// ---------------- fp16 1-pass mma GEMM (R14-proven core, occupancy pinned) ----------------
#define RS 20
#define PLANE 2560
#define STG_BYTES 20480
#define MMA_SMEM_BYTES (2 * STG_BYTES)

__device__ __forceinline__ void gemm_body(
    const uint32_t* pA, const uint32_t* pB,
    int mbase, int nbase, int K, const float* bias, float* C, int ldC, int accum,
    uint32_t smb) {
    const int tid = threadIdx.x;
    const int w = tid >> 5, lane = tid & 31;
    const int warpM = w & 1, warpN = w >> 1;
    const int Kw = K >> 1;
    const int nCh = Kw >> 4;

    float acc[4][4][4];
#pragma unroll
    for (int i = 0; i < 4; i++)
#pragma unroll
        for (int j = 0; j < 4; j++)
#pragma unroll
            for (int q = 0; q < 4; q++) acc[i][j][q] = 0.f;

    const int lrow = lane & 15, lcol = lane >> 4;
    uint32_t aAddr[4], bAddr[2];
#pragma unroll
    for (int i = 0; i < 4; i++)
        aAddr[i] = smb + (uint32_t)(((warpM * 64 + i * 16 + lrow) * RS + lcol * 4) * 4);
#pragma unroll
    for (int jp = 0; jp < 2; jp++)
        bAddr[jp] = smb + (uint32_t)(PLANE * 4 + ((warpN * 32 + jp * 16 + lrow) * RS + lcol * 4) * 4);

#define ISSUE(tw) do {                                                            \
    const int kw0 = (tw) * 16;                                                    \
    const uint32_t sb = smb + (uint32_t)(((tw) & 1) * STG_BYTES);                 \
    _Pragma("unroll")                                                             \
    for (int q = 0; q < 4; q++) {                                                 \
        const int pl = q >> 1;                                                    \
        int s = tid + (q & 1) * 256;                                              \
        int r = s >> 2, sg = s & 3;                                               \
        const uint32_t* src = (pl == 0 ? pA : pB)                                 \
            + (size_t)((pl == 0 ? mbase : nbase) + r) * Kw + kw0 + sg * 4;        \
        uint32_t dst = sb + (uint32_t)((pl * PLANE + r * RS + sg * 4) * 4);       \
        CP_ASYNC16(dst, src);                                                     \
    }                                                                             \
    CP_COMMIT(); } while (0)

    ISSUE(0);
    if (nCh > 1) ISSUE(1);

    for (int t = 0; t < nCh; t++) {
        if (t + 1 < nCh) CP_WAIT1(); else CP_WAIT0();
        __syncthreads();

        const uint32_t so = (uint32_t)((t & 1) * STG_BYTES);
#pragma unroll
        for (int ks = 0; ks < 2; ks++) {
            const uint32_t ko = so + ks * 32;
            uint32_t Bf[4][2];
#pragma unroll
            for (int jp = 0; jp < 2; jp++) {
                LDSM_X4(Bf[2 * jp][0], Bf[2 * jp + 1][0], Bf[2 * jp][1], Bf[2 * jp + 1][1],
                        bAddr[jp] + ko);
            }
#pragma unroll
            for (int i = 0; i < 4; i++) {
                uint32_t A0, A1, A2, A3;
                LDSM_X4(A0, A1, A2, A3, aAddr[i] + ko);
#pragma unroll
                for (int j = 0; j < 4; j++)
                    MMA_F16(acc[i][j], A0, A1, A2, A3, Bf[j][0], Bf[j][1]);
            }
        }
        if (t + 2 < nCh) {
            __syncthreads();
            ISSUE(t + 2);
        }
    }
#undef ISSUE

    const int g = lane >> 2, tg = lane & 3;
#pragma unroll
    for (int i = 0; i < 4; i++) {
#pragma unroll
        for (int j = 0; j < 4; j++) {
            int row = mbase + warpM * 64 + i * 16 + g;
            int col = nbase + warpN * 32 + j * 8 + tg * 2;
            float* c0p = C + (size_t)row * ldC + col;
            float* c1p = C + (size_t)(row + 8) * ldC + col;
            float a0 = acc[i][j][0], a1 = acc[i][j][1];
            float a2 = acc[i][j][2], a3 = acc[i][j][3];
            if (accum) {
                float2 e0 = *(float2*)c0p, e1 = *(float2*)c1p;
                a0 += e0.x; a1 += e0.y; a2 += e1.x; a3 += e1.y;
            } else {
                float b0v = bias[col], b1v = bias[col + 1];
                a0 += b0v; a1 += b1v; a2 += b0v; a3 += b1v;
            }
            *(float2*)c0p = make_float2(a0, a1);
            *(float2*)c1p = make_float2(a2, a3);
        }
    }
}

__global__ void __launch_bounds__(256, 2)
mma_gemm(const __half* __restrict__ A, const __half* __restrict__ B,
         const float* __restrict__ bias, float* __restrict__ C, int ldC, int K, int accum) {
    extern __shared__ uint32_t sm[];
    gemm_body((const uint32_t*)A, (const uint32_t*)B,
              blockIdx.y * 128, blockIdx.x * 128, K, bias, C, ldC, accum, smem_u32(sm));
}

// dual: bx<12 -> IOU accum (A1@B1 += C1, ldC 2048); bx>=12 -> HW (A2@B2 + bias2, ldC 512)
__global__ void __launch_bounds__(256, 2)
mma_gemm_dual(const __half* __restrict__ A1, const __half* __restrict__ A2,
              const __half* __restrict__ B1, const __half* __restrict__ B2,
              const float* __restrict__ bias2, float* __restrict__ C1, float* __restrict__ C2) {
    extern __shared__ uint32_t sm[];
    if (blockIdx.x < 12) {
        gemm_body((const uint32_t*)A1, (const uint32_t*)B1,
                  blockIdx.y * 128, blockIdx.x * 128, 512, nullptr, C1, 2048, 1, smem_u32(sm));
    } else {
        gemm_body((const uint32_t*)A2, (const uint32_t*)B2,
                  blockIdx.y * 128, (blockIdx.x - 12) * 128, 512, bias2, C2, 512, 0, smem_u32(sm));
    }
}

// ---------------- prep: tiled transpose -> fp16 ----------------
__global__ void __launch_bounds__(256)
transp_h(const float* __restrict__ srcA, const float* __restrict__ srcB,
         int ldA, int ldB, int nsplit, int K, __half* __restrict__ dst) {
    __shared__ float tile[32][33];
    const int n0 = blockIdx.x * 32, k0 = blockIdx.y * 32;
    const int tx = threadIdx.x, ty = threadIdx.y;
    const int n = n0 + tx;
    const float* src = (n0 < nsplit) ? srcA : srcB;
    const int ld = (n0 < nsplit) ? ldA : ldB;
    const int col = (n0 < nsplit) ? n : n - nsplit;
#pragma unroll
    for (int i = 0; i < 4; i++) {
        int k = k0 + ty + i * 8;
        tile[ty + i * 8][tx] = src[(size_t)k * ld + col];
    }
    __syncthreads();
    const int Kw = K >> 1;
#pragma unroll
    for (int j = 0; j < 2; j++) {
        int lin = j * 256 + ty * 32 + tx;
        int nl = lin >> 4, kp = lin & 15;
        uint32_t h = f2h(tile[kp * 2][nl], tile[kp * 2 + 1][nl]);
        ((uint32_t*)dst)[(size_t)(n0 + nl) * Kw + (k0 >> 1) + kp] = h;
    }
}

// wih fp16 + biases + zero-inits (merged)
__global__ void prep_init(const float* __restrict__ wih_f, const float* __restrict__ wih_b,
                          const float* __restrict__ bioux, const float* __restrict__ biouh,
                          const float* __restrict__ bfx,
                          const float* __restrict__ bih_f, const float* __restrict__ bih_b) {
    int idx = blockIdx.x * blockDim.x + threadIdx.x;
    const int T2 = G3M * (MM / 2);
    if (idx < 2 * T2) {
        int dir = idx / T2, j = idx % T2;
        const float* wsrc = dir ? wih_b : wih_f;
        ((uint32_t*)g_wih[dir])[j] = f2h(wsrc[2 * j], wsrc[2 * j + 1]);
    }
    if (idx < 2048)
        g_biasbig[idx] = (idx < G3M) ? (bioux[idx] + biouh[idx]) : bfx[idx - G3M];
    if (idx < 2 * G3M)
        g_bihcat[idx] = (idx < G3M) ? bih_f[idx] : bih_b[idx - G3M];
    if (idx == 0) g_bar = 0u;
    if (idx < MM / 2)
        ((uint32_t*)g_Hhi)[idx] = 0u;          // zero slot h
    if (idx < 2 * BB * MM) (&g_hst[0][0])[idx] = 0.f;
}

// ---------------- merged embed gathers: leaf h (hi-only) + x for all levels ----------------
#define LEAF_CNT (NLEAF * (MM / 4))
__global__ void gather_embed(const float* __restrict__ embed,
                             const int* __restrict__ leaf_idx,
                             const int* __restrict__ lwi) {
    int idx = blockIdx.x * blockDim.x + threadIdx.x;
    if (idx < LEAF_CNT) {
        int n = idx >> 7, m = (idx & 127) * 4;
        int w = leaf_idx[n];
        float4 v = *(const float4*)(embed + (size_t)w * MM + m);
        size_t wrd = ((size_t)(1 + n) * MM + m) >> 1;
        ((uint32_t*)g_Hhi)[wrd]     = f2h(v.x, v.y);
        ((uint32_t*)g_Hhi)[wrd + 1] = f2h(v.z, v.w);
        return;
    }
    int r = idx - LEAF_CNT;
    if (r >= NALL * (MM / 4)) return;
    int ng = r >> 7, m = (r & 127) * 4;
    int w = lwi[ng];
    float4 x = *(const float4*)(embed + (size_t)w * MM + m);
    size_t wrd = ((size_t)ng * MM + m) >> 1;
    ((uint32_t*)g_Xall)[wrd]     = f2h(x.x, x.y);
    ((uint32_t*)g_Xall)[wrd + 1] = f2h(x.z, x.w);
}

// ---------------- per-level gather: sum of child h (hi-only) ----------------
__global__ void gather_level(const int* __restrict__ child, int d) {
    int idx = blockIdx.x * blockDim.x + threadIdx.x;
    if (idx >= NNODE * (MM / 4)) return;
    int n = idx >> 7, m = (idx & 127) * 4;
    float4 s = make_float4(0.f, 0.f, 0.f, 0.f);
    const int* ch = child + ((size_t)d * NNODE + n) * KCH;
#pragma unroll
    for (int k = 0; k < KCH; k++) {
        int ci = ch[k];
        size_t wrd = ((size_t)ci * MM + m) >> 1;
        uint2 hw = *(const uint2*)((const uint32_t*)g_Hhi + wrd);
        float2 a0 = h2f(hw.x), a1 = h2f(hw.y);
        s.x += a0.x; s.y += a0.y; s.z += a1.x; s.w += a1.y;
    }
    size_t wrd = ((size_t)n * MM + m) >> 1;
    ((uint32_t*)g_SUMH)[wrd]     = f2h(s.x, s.y);
    ((uint32_t*)g_SUMH)[wrd + 1] = f2h(s.z, s.w);
}

// ---------------- level pointwise ----------------
__global__ void level_point(const int* __restrict__ child, int d) {
    int idx = blockIdx.x * blockDim.x + threadIdx.x;
    if (idx >= NNODE * (MM / 2)) return;
    int n = idx >> 8, j = idx & 255;
    int m = 2 * j;
    const float* row = g_IOUFall + (size_t)(d * NNODE + n) * 2048;
    float2 iv = *(const float2*)(row + m);
    float2 ov = *(const float2*)(row + MM + m);
    float2 uv = *(const float2*)(row + 2 * MM + m);
    float2 fx = *(const float2*)(row + 3 * MM + m);
    float c0 = sigf(iv.x) * tanhf(uv.x);
    float c1 = sigf(iv.y) * tanhf(uv.y);
    const int* ch = child + ((size_t)d * NNODE + n) * KCH;
#pragma unroll
    for (int k = 0; k < KCH; k++) {
        int ci = ch[k];
        if (ci > NLEAF) {
            float2 hw = *(const float2*)(g_HW + (size_t)ci * MM + m);
            float2 cc = *(const float2*)(g_c_pool + (size_t)ci * MM + m);
            c0 += sigf(fx.x + hw.x) * cc.x;
            c1 += sigf(fx.y + hw.y) * cc.y;
        }
    }
    float h0 = sigf(ov.x) * tanhf(c0);
    float h1 = sigf(ov.y) * tanhf(c1);
    size_t slot = (size_t)(OFFS + d * NNODE + n) * MM + m;
    *(float2*)(g_c_pool + slot) = make_float2(c0, c1);
    ((uint32_t*)g_Hhi)[slot >> 1] = f2h(h0, h1);
}

// ---------------- GRU ----------------
// xs = gathered pool h; Hhi already fp16, so this is a pure word copy
__global__ void gather_xs(const int* __restrict__ ctx) {
    int idx = blockIdx.x * blockDim.x + threadIdx.x;
    if (idx >= BB * SSEQ * (MM / 4)) return;
    int rowI = idx >> 7, m = (idx & 127) * 4;
    int p = ctx[rowI];
    size_t swrd = ((size_t)p * MM + m) >> 1;
    uint2 hw = *(const uint2*)((const uint32_t*)g_Hhi + swrd);
    size_t wrd = ((size_t)rowI * MM + m) >> 1;
    ((uint32_t*)g_xs)[wrd]     = hw.x;
    ((uint32_t*)g_xs)[wrd + 1] = hw.y;
}

#define GNB 96
#define HS_STR 516
// R14-proven barrier (atomic poll + nanosleep backoff)
__device__ __forceinline__ void gridbar(unsigned gen) {
    __syncthreads();
    if (threadIdx.x == 0) {
        __threadfence();
        atomicAdd(&g_bar, 1u);
        while (atomicAdd(&g_bar, 0u) < gen * GNB) { __nanosleep(64); }
        __threadfence();
    }
    __syncthreads();
}

__global__ void __launch_bounds__(256) gru_persist(const float* __restrict__ whh_f,
                                                   const float* __restrict__ whh_b,
                                                   const float* __restrict__ bhh_f,
                                                   const float* __restrict__ bhh_b,
                                                   float* __restrict__ out) {
    extern __shared__ float sh[];
    float* Hs = sh;                     // 64 x HS_STR
    float* Ws = sh + 64 * HS_STR;       // k-major [512][32]
    const int dir = blockIdx.y;
    const int n0 = blockIdx.x * 32;
    const int tid = threadIdx.x;
    const int bid = blockIdx.y * 48 + blockIdx.x;
    const float* whh = dir ? whh_b : whh_f;
    const float* bhh = dir ? bhh_b : bhh_f;

    for (int i = tid; i < 32 * 512; i += 256) {
        int k = i & 511, col = i >> 9;
        Ws[k * 32 + col] = whh[(size_t)(n0 + col) * MM + k];
    }
    const int cg = tid & 7, r = tid >> 3;
    float bv[4];
#pragma unroll
    for (int c = 0; c < 4; c++) bv[c] = bhh[n0 + cg * 4 + c];

    unsigned gen = 0;
    for (int t = 0; t < SSEQ; t++) {
        __syncthreads();
        const float* H = g_hst[dir];
        for (int i = tid; i < 64 * 512; i += 256) Hs[(i >> 9) * HS_STR + (i & 511)] = H[i];
        __syncthreads();
        int row0 = 2 * r, row1 = row0 + 1;
        float acc0[4] = {0.f, 0.f, 0.f, 0.f};
        float acc1[4] = {0.f, 0.f, 0.f, 0.f};
        for (int k = 0; k < 512; k += 4) {
            float4 ha = *(float4*)&Hs[row0 * HS_STR + k];
            float4 hb = *(float4*)&Hs[row1 * HS_STR + k];
#pragma unroll
            for (int i = 0; i < 4; i++) {
                float4 wv = *(float4*)&Ws[(k + i) * 32 + cg * 4];
                float a = (&ha.x)[i], b = (&hb.x)[i];
                acc0[0] += a * wv.x; acc0[1] += a * wv.y; acc0[2] += a * wv.z; acc0[3] += a * wv.w;
                acc1[0] += b * wv.x; acc1[1] += b * wv.y; acc1[2] += b * wv.z; acc1[3] += b * wv.w;
            }
        }
#pragma unroll
        for (int c = 0; c < 4; c++) {
            int n = n0 + cg * 4 + c;
            g_hg[dir][(size_t)row0 * G3M + n] = acc0[c] + bv[c];
            g_hg[dir][(size_t)row1 * G3M + n] = acc1[c] + bv[c];
        }
        gridbar(++gen);
        for (int e = bid * 256 + tid; e < 2 * BB * MM; e += GNB * 256) {
            int dd = e >> 15;
            int rem = e & 32767;
            int b = rem >> 9, j = rem & 511;
            int pos = dd ? (SSEQ - 1 - t) : t;
            const float* xrow = g_xg + (size_t)(b * SSEQ + pos) * (2 * G3M) + dd * G3M;
            const float* hrow = g_hg[dd] + (size_t)b * G3M;
            float rr_ = sigf(xrow[j] + hrow[j]);
            float zz = sigf(xrow[MM + j] + hrow[MM + j]);
            float nn = tanhf(xrow[2 * MM + j] + rr_ * hrow[2 * MM + j]);
            float hp = g_hst[dd][b * MM + j];
            float hn = (1.f - zz) * nn + zz * hp;
            g_hst[dd][b * MM + j] = hn;
            float* op = out + (size_t)(b * SSEQ + pos) * MM + j;
            if (t < 8) *op = hn; else *op += hn;
        }
        gridbar(++gen);
    }
}

// ---------------- host launch ----------------
extern "C" void kernel_launch(void* const* d_in, const int* in_sizes, int n_in,
                              void* d_out, int out_size) {
    const float* embed   = (const float*)d_in[0];
    const float* Wioux   = (const float*)d_in[1];
    const float* bioux   = (const float*)d_in[2];
    const float* Wiouh   = (const float*)d_in[3];
    const float* biouh   = (const float*)d_in[4];
    const float* Wfx     = (const float*)d_in[5];
    const float* bfx     = (const float*)d_in[6];
    const float* Wfh     = (const float*)d_in[7];
    const float* bfh     = (const float*)d_in[8];
    const float* wih_f   = (const float*)d_in[9];
    const float* whh_f   = (const float*)d_in[10];
    const float* bih_f   = (const float*)d_in[11];
    const float* bhh_f   = (const float*)d_in[12];
    const float* wih_b   = (const float*)d_in[13];
    const float* whh_b   = (const float*)d_in[14];
    const float* bih_b   = (const float*)d_in[15];
    const float* bhh_b   = (const float*)d_in[16];

    const int* leaf_idx = nullptr; const int* level_idx = nullptr;
    const int* child = nullptr; const int* ctx = nullptr;
    for (int i = 17; i < n_in; i++) {
        int sz = in_sizes[i];
        if (sz == NLEAF)                 leaf_idx  = (const int*)d_in[i];
        else if (sz == DD * NNODE)       level_idx = (const int*)d_in[i];
        else if (sz == DD * NNODE * KCH) child     = (const int*)d_in[i];
        else if (sz == BB * SSEQ)        ctx       = (const int*)d_in[i];
    }

    float* out = (float*)d_out;

    const size_t GRU_SMEM = (64 * HS_STR + 512 * 32) * sizeof(float);
    cudaFuncSetAttribute(mma_gemm, cudaFuncAttributeMaxDynamicSharedMemorySize, MMA_SMEM_BYTES);
    cudaFuncSetAttribute(mma_gemm_dual, cudaFuncAttributeMaxDynamicSharedMemorySize, MMA_SMEM_BYTES);
    cudaFuncSetAttribute(gru_persist, cudaFuncAttributeMaxDynamicSharedMemorySize, (int)GRU_SMEM);

    __half* d_Hhi;  cudaGetSymbolAddress((void**)&d_Hhi, g_Hhi);
    __half* d_X;    cudaGetSymbolAddress((void**)&d_X, g_Xall);
    __half* d_SH;   cudaGetSymbolAddress((void**)&d_SH, g_SUMH);
    __half* d_W1;   cudaGetSymbolAddress((void**)&d_W1, g_W1);
    __half* d_W2;   cudaGetSymbolAddress((void**)&d_W2, g_W2);
    __half* d_WfT;  cudaGetSymbolAddress((void**)&d_WfT, g_WfT);
    __half* d_wih;  cudaGetSymbolAddress((void**)&d_wih, g_wih);
    __half* d_xs;   cudaGetSymbolAddress((void**)&d_xs, g_xs);
    float* d_IOUF;  cudaGetSymbolAddress((void**)&d_IOUF, g_IOUFall);
    float* d_HW;    cudaGetSymbolAddress((void**)&d_HW, g_HW);
    float* d_bb;    cudaGetSymbolAddress((void**)&d_bb, g_biasbig);
    float* d_bih;   cudaGetSymbolAddress((void**)&d_bih, g_bihcat);
    float* d_xg;    cudaGetSymbolAddress((void**)&d_xg, g_xg);

    // prep + init
    {
        dim3 blk(32, 8);
        transp_h<<<dim3(2048 / 32, 512 / 32), blk>>>(Wioux, Wfx, G3M, MM, G3M, 512, d_W1);
        transp_h<<<dim3(G3M / 32, 512 / 32), blk>>>(Wiouh, nullptr, G3M, 0, G3M, 512, d_W2);
        transp_h<<<dim3(MM / 32, 512 / 32), blk>>>(Wfh, nullptr, MM, 0, MM, 512, d_WfT);
    }
    prep_init<<<(2 * G3M * (MM / 2) + 255) / 256, 256>>>(wih_f, wih_b, bioux, biouh, bfx,
                                                         bih_f, bih_b);
    gather_embed<<<(LEAF_CNT + NALL * (MM / 4) + 255) / 256, 256>>>(embed, leaf_idx, level_idx);

    // upfront: IOUF_all = X_all @ [Wioux|Wfx]^T + biasbig
    {
        dim3 grid(2048 / 128, NALL / 128);
        mma_gemm<<<grid, 256, MMA_SMEM_BYTES>>>(d_X, d_W1, d_bb, d_IOUF, 2048, 512, 0);
    }

    // level 0: IOU accum only
    gather_level<<<(NNODE * (MM / 4) + 255) / 256, 256>>>(child, 0);
    {
        dim3 grid(G3M / 128, NNODE / 128);
        mma_gemm<<<grid, 256, MMA_SMEM_BYTES>>>(d_SH, d_W2, nullptr, d_IOUF, 2048, 512, 1);
    }
    level_point<<<(NNODE * (MM / 2) + 255) / 256, 256>>>(child, 0);

    // levels 1..7: fused [IOU(d) accum | HW(d-1)]
    for (int d = 1; d < DD; d++) {
        gather_level<<<(NNODE * (MM / 4) + 255) / 256, 256>>>(child, d);
        size_t hoff = (size_t)(OFFS + (d - 1) * NNODE) * MM;
        {
            dim3 grid(16, NNODE / 128);
            mma_gemm_dual<<<grid, 256, MMA_SMEM_BYTES>>>(
                d_SH, d_Hhi + hoff, d_W2, d_WfT,
                bfh, d_IOUF + (size_t)d * NNODE * 2048, d_HW + hoff);
        }
        level_point<<<(NNODE * (MM / 2) + 255) / 256, 256>>>(child, d);
    }

    // GRU input gates: single GEMM, N=3072
    gather_xs<<<(BB * SSEQ * (MM / 4) + 255) / 256, 256>>>(ctx);
    {
        dim3 grid(2 * G3M / 128, (BB * SSEQ) / 128);
        mma_gemm<<<grid, 256, MMA_SMEM_BYTES>>>(d_xs, d_wih, d_bih, d_xg, 2 * G3M, 512, 0);
    }

    // GRU recurrence
    {
        dim3 grid(48, 2);
        gru_persist<<<grid, 256, GRU_SMEM>>>(whh_f, whh_b, bhh_f, bhh_b, out);
    }
}